// round 11
// baseline (speedup 1.0000x reference)
#include <cuda_runtime.h>
#include <cuda_bf16.h>
#include <cstddef>

// hungarian_matcher cost kernel
// out[b, q, j] = 5 * sum_d |pred_boxes[b,q,d] - target_boxes[b*64+j, d]|
//              - softmax(pred_logits[b,q,:])[target_ids[b*64+j]]
//
// R11: fat-CTA layout. grid (9,16) = 144 CTAs (one wave, ~1 CTA/SM),
// block 1024 = 64 j-lanes x 16 qy. Each CTA owns batch b and 100 queries:
// targets staged ONCE, one barrier, one LDG-latency exposure (vs 5x in the
// 720-CTA layout). Main loop = R10's vectorized stream: 3 broadcast
// LDS.128 per pred row, 3 LDS.128 target box, FADD-with-abs, coalesced
// scalar STG. Query map q = qy + 16k balances warps (6-7 iters each).

namespace {

constexpr int BOX  = 11;
constexpr int BOXP = 12;          // padded row (48B, float4-aligned)
constexpr int NC   = 4;
constexpr int PER  = 64;
constexpr int QY   = 16;
constexpr int NT   = PER * QY;    // 1024 threads
constexpr int QPC  = 100;         // queries per CTA (900 = 9*100)
constexpr int QPT  = 7;           // ceil(100/16) loop bound

__global__ __launch_bounds__(NT)
void matcher_kernel(const float* __restrict__ logits,
                    const float* __restrict__ boxes,
                    const float* __restrict__ tboxes,
                    const int*   __restrict__ tids,
                    float* __restrict__ out,
                    int nq)
{
    const int b  = blockIdx.y;
    const int q0 = blockIdx.x * QPC;
    const int j  = threadIdx.x;           // target 0..63
    const int qy = threadIdx.y;           // 0..15
    const int t  = qy * PER + j;          // linear tid 0..1023

    __shared__ float s_tb[PER * BOXP];          // 768 floats
    __shared__ float s_pb[QPC * BOXP];          // 1200 floats
    __shared__ float s_negprob[QPC * NC];       // 400 floats

    // --- Target boxes: one round (704 < 1024 lanes), padded STS ---
    if (t < PER * BOX) {
        const int row = t / BOX, col = t - row * BOX;
        s_tb[row * BOXP + col] = tboxes[(size_t)b * PER * BOX + t];
    }

    // --- Pred boxes: 1100 elems, 2 rounds, coalesced LDG, padded STS ---
    for (int i = t; i < QPC * BOX; i += NT) {
        const int row = i / BOX, col = i - row * BOX;
        s_pb[row * BOXP + col] = boxes[((size_t)b * nq + q0) * BOX + i];
    }

    // --- Softmax rows: thread t < QPC handles query q0+t ---
    if (t < QPC) {
        const float* lp = logits + ((size_t)b * nq + q0 + t) * NC;
        float l[NC];
        float m = -1e30f;
#pragma unroll
        for (int c = 0; c < NC; c++) { l[c] = lp[c]; m = fmaxf(m, l[c]); }
        float s = 0.0f;
#pragma unroll
        for (int c = 0; c < NC; c++) { l[c] = __expf(l[c] - m); s += l[c]; }
        const float inv = __frcp_rn(s);
#pragma unroll
        for (int c = 0; c < NC; c++) s_negprob[t * NC + c] = -l[c] * inv;
    }

    // Class id (L1-resident, coalesced across j)
    const int cls = tids[b * PER + j];

    __syncthreads();

    // --- Target box -> registers: 3 LDS.128, conflict-free (stride 48B) ---
    float tb[BOXP];
    {
        const float4* tr = (const float4*)(s_tb + j * BOXP);
#pragma unroll
        for (int v = 0; v < 3; v++) ((float4*)tb)[v] = tr[v];
    }

    // --- Up to 7 query rows: q_local = qy + 16k (balanced across warps) ---
    float* obase = out + ((size_t)b * nq + q0) * PER + j;
#pragma unroll
    for (int k = 0; k < QPT; k++) {
        const int ql = qy + (k << 4);
        if (ql < QPC) {
            float pbf[BOXP];
            {
                const float4* pr = (const float4*)(s_pb + ql * BOXP);
#pragma unroll
                for (int v = 0; v < 3; v++) ((float4*)pbf)[v] = pr[v];
            }

            float sa = 0.0f, sb = 0.0f;
#pragma unroll
            for (int d = 0; d < BOX; d += 2) {
                sa += fabsf(pbf[d] - tb[d]);
                if (d + 1 < BOX) sb += fabsf(pbf[d + 1] - tb[d + 1]);
            }
            obase[(size_t)ql * PER] =
                fmaf(5.0f, sa + sb, s_negprob[ql * NC + cls]);
        }
    }
}

} // namespace

extern "C" void kernel_launch(void* const* d_in, const int* in_sizes, int n_in,
                              void* d_out, int out_size)
{
    const float* logits = (const float*)d_in[0];
    const float* boxes  = (const float*)d_in[1];
    const float* tboxes = (const float*)d_in[2];
    const int*   tids   = (const int*)d_in[3];
    float* out = (float*)d_out;

    const int n_total = in_sizes[3];                 // 1024
    const int box_dim = in_sizes[2] / n_total;       // 11
    const int bsnq    = in_sizes[1] / box_dim;       // 14400
    const int per     = out_size / bsnq;             // 64
    const int bs      = n_total / per;               // 16
    const int nq      = bsnq / bs;                   // 900

    (void)n_in; (void)box_dim; (void)per;

    dim3 block(PER, QY);
    dim3 grid(nq / QPC, bs);                         // (9, 16) = 144
    matcher_kernel<<<grid, block>>>(logits, boxes, tboxes, tids, out, nq);
}